// round 13
// baseline (speedup 1.0000x reference)
#include <cuda_runtime.h>
#include <cstdint>

#define CCH 64
#define HH 128
#define WW 128
#define NBATCH 32
#define KW 7
#define NTHREADS 1024
#define TOTAL_ROWS (NBATCH * HH)
#define HW (HH * WW)

// smem layout (bytes)
#define B_BYTES (KW * 8 * 4 * 32 * 16)        // 114688: [j][kt][ntp][lane] uint4
#define TOFF B_BYTES
#define T_STRIDE 68                            // uint32 per T row (64 ci + 4 pad)
#define T_ROWS 152
#define T_BYTES (T_ROWS * T_STRIDE * 4)        // 41344
#define CONVOFF (TOFF + T_BYTES)
#define BUF_STRIDE 132                         // floats per co row (128 + 4 pad)
#define BUF_BYTES (CCH * BUF_STRIDE * 4)       // 33792
#define T4OFF (CONVOFF + BUF_BYTES)
#define SMEM_DYN (T4OFF + BUF_BYTES)           // 223616

__device__ __forceinline__ uint32_t f2tf32(float f) {
    uint32_t r;
    asm("cvt.rna.tf32.f32 %0, %1;" : "=r"(r) : "f"(f));
    return r;
}

__device__ __forceinline__ void mma_tf32(float* d,
                                         uint32_t a0, uint32_t a1,
                                         uint32_t a2, uint32_t a3,
                                         uint32_t b0, uint32_t b1) {
    asm volatile(
        "mma.sync.aligned.m16n8k8.row.col.f32.tf32.tf32.f32 "
        "{%0,%1,%2,%3}, {%4,%5,%6,%7}, {%8,%9}, {%0,%1,%2,%3};"
        : "+f"(d[0]), "+f"(d[1]), "+f"(d[2]), "+f"(d[3])
        : "r"(a0), "r"(a1), "r"(a2), "r"(a3), "r"(b0), "r"(b1));
}

// Stage x[n][:, h, :] -> T as tf32, transposed [w+9][ci]. 512 threads (ids 0..511).
__device__ __forceinline__ void stage_T(char* smem, const float* __restrict__ x,
                                        int n, int h, int id) {
    uint32_t* Tb = (uint32_t*)(smem + TOFF);
    const float* xrow = x + ((size_t)(n * CCH) * HH + h) * WW;
    const int ci = id & 63;
    const int w0 = id >> 6;                    // 0..7
    #pragma unroll
    for (int it = 0; it < 4; ++it) {
        const int wg = w0 + 8 * it;            // 0..31
        const float4 v = __ldg((const float4*)(xrow + (size_t)ci * HW + wg * 4));
        uint32_t* dst = Tb + (4 * wg + 9) * T_STRIDE + ci;
        dst[0 * T_STRIDE] = f2tf32(v.x);
        dst[1 * T_STRIDE] = f2tf32(v.y);
        dst[2 * T_STRIDE] = f2tf32(v.z);
        dst[3 * T_STRIDE] = f2tf32(v.w);
    }
}

extern "C" __global__ void __launch_bounds__(NTHREADS, 1)
fused_conv_mma_kernel(const float* __restrict__ x,
                      const float* __restrict__ wconv,
                      const float* __restrict__ p4,
                      float* __restrict__ out) {
    extern __shared__ char smem[];
    const int tid = threadIdx.x;
    const int lane = tid & 31;
    const int warp = tid >> 5;                 // 0..31
    const int kh = warp >> 4;                  // K-half (0: s 0..27, 1: s 28..55)
    const int g  = (warp >> 3) & 1;            // co-half (0: co 0..31, 1: 32..63)
    const int mw = warp & 7;                   // m-stripe (16 w rows)

    // ---- one-time: pack B fragments [j][kt][ntp][lane] = uint4 ----
    for (int idx = tid; idx < KW * 8 * 4 * 32; idx += NTHREADS) {
        const int t   = idx & 31;
        const int ntp = (idx >> 5) & 3;
        const int kt  = (idx >> 7) & 7;
        const int j   = idx >> 10;
        const int n_in = t >> 2;
        const int k_in = t & 3;
        const int ci0 = kt * 8 + k_in, ci1 = ci0 + 4;
        const int coA = 16 * ntp + n_in, coB = coA + 8;
        uint4 v;
        v.x = f2tf32(__ldg(wconv + (coA * CCH + ci0) * KW + j));
        v.y = f2tf32(__ldg(wconv + (coA * CCH + ci1) * KW + j));
        v.z = f2tf32(__ldg(wconv + (coB * CCH + ci0) * KW + j));
        v.w = f2tf32(__ldg(wconv + (coB * CCH + ci1) * KW + j));
        ((uint4*)smem)[idx] = v;
    }
    // zero T (pad rows stay zero forever)
    for (int i = tid; i < T_ROWS * T_STRIDE; i += NTHREADS)
        ((uint32_t*)(smem + TOFF))[i] = 0;

    const float p40 = __ldg(p4 + 0), p41 = __ldg(p4 + 1), p42 = __ldg(p4 + 2);

    __syncthreads();
    int row = blockIdx.x;
    if (row < TOTAL_ROWS && tid < 512)
        stage_T(smem, x, row >> 7, row & (HH - 1), tid);
    __syncthreads();

    const uint4* Bfr = (const uint4*)smem;
    float* convbuf = (float*)(smem + CONVOFF);
    float* t4buf   = (float*)(smem + T4OFF);

    while (row < TOTAL_ROWS) {
        const int n = row >> 7;
        const int h = row & (HH - 1);
        const float* xb = x + (size_t)n * CCH * HW;
        float* ob = out + (size_t)n * CCH * HW;
        const int hm1 = (h - 1 + HH) & (HH - 1);
        const int r0 = hm1 - 2, r2 = hm1 + 2;
        const bool has0 = (r0 >= 0), has2 = (r2 < HH);

        // ---- MMA: partial conv[w][co], m-stripe mw, co-half g, K-half kh ----
        float acc[4][4];
        #pragma unroll
        for (int nt = 0; nt < 4; ++nt)
            #pragma unroll
            for (int q = 0; q < 4; ++q) acc[nt][q] = 0.0f;

        {
            const uint32_t* Tb = (const uint32_t*)(smem + TOFF);
            const int rbase = mw * 16 + (lane >> 2);
            const int cbase = lane & 3;
            const int s0 = 28 * kh;
            #pragma unroll 4
            for (int s = s0; s < s0 + 28; ++s) {
                const int j = s >> 3;
                const int kt = s & 7;
                const uint32_t* Tc =
                    Tb + (rbase + 3 * j) * T_STRIDE + cbase + kt * 8;
                const uint32_t a0 = Tc[0];
                const uint32_t a1 = Tc[8 * T_STRIDE];
                const uint32_t a2 = Tc[4];
                const uint32_t a3 = Tc[8 * T_STRIDE + 4];
                const uint4* Bj = Bfr + j * 1024 + kt * 128 + 64 * g + lane;
                const uint4 b01 = Bj[0];
                const uint4 b23 = Bj[32];
                mma_tf32(acc[0], a0, a1, a2, a3, b01.x, b01.y);
                mma_tf32(acc[1], a0, a1, a2, a3, b01.z, b01.w);
                mma_tf32(acc[2], a0, a1, a2, a3, b23.x, b23.y);
                mma_tf32(acc[3], a0, a1, a2, a3, b23.z, b23.w);
            }
        }

        if (kh == 0) {
            // ---- dump K-half-0 partials to convbuf[co][w] ----
            #pragma unroll
            for (int half = 0; half < 2; ++half) {
                const int w = mw * 16 + half * 8 + (lane >> 2);
                #pragma unroll
                for (int nt = 0; nt < 4; ++nt)
                    #pragma unroll
                    for (int q = 0; q < 2; ++q) {
                        const int co = 32 * g + nt * 8 + 2 * (lane & 3) + q;
                        convbuf[co * BUF_STRIDE + w] = acc[nt][half * 2 + q];
                    }
            }
        } else {
            // ---- t4 into t4buf[co][w] (16 warps, coalesced LDG) ----
            const int wt = warp - 16;          // 0..15
            #pragma unroll
            for (int i = 0; i < 4; ++i) {
                const int co = wt + 16 * i;
                const float* xc = xb + (size_t)co * HW;
                #pragma unroll
                for (int k = 0; k < 4; ++k) {
                    const int win = lane + 32 * k;
                    float t4v = p41 * __ldg(xc + hm1 * WW + win);
                    if (has0) t4v = fmaf(p40, __ldg(xc + r0 * WW + win), t4v);
                    if (has2) t4v = fmaf(p42, __ldg(xc + r2 * WW + win), t4v);
                    t4buf[co * BUF_STRIDE + ((win - 2) & (WW - 1))] = t4v;
                }
            }
        }

        __syncthreads();

        const int nrow = row + gridDim.x;
        if (kh == 1) {
            // ---- merge K-half-1 partials into convbuf ----
            #pragma unroll
            for (int half = 0; half < 2; ++half) {
                const int w = mw * 16 + half * 8 + (lane >> 2);
                #pragma unroll
                for (int nt = 0; nt < 4; ++nt)
                    #pragma unroll
                    for (int q = 0; q < 2; ++q) {
                        const int co = 32 * g + nt * 8 + 2 * (lane & 3) + q;
                        float* p = convbuf + co * BUF_STRIDE + w;
                        *p += acc[nt][half * 2 + q];
                    }
            }
        } else {
            // ---- stage next row (16 warps, overlaps merge) ----
            if (nrow < TOTAL_ROWS)
                stage_T(smem, x, nrow >> 7, nrow & (HH - 1), tid);
        }

        __syncthreads();

        // ---- out phase: coalesced float4, all 32 warps ----
        #pragma unroll
        for (int i = 0; i < 2; ++i) {
            const int co = warp + 32 * i;
            const float4 cv = *(const float4*)(convbuf + co * BUF_STRIDE + 4 * lane);
            const float4 tv = *(const float4*)(t4buf + co * BUF_STRIDE + 4 * lane);
            const float4 xv = __ldg((const float4*)(xb + (size_t)co * HW + h * WW + 4 * lane));
            float4 ov;
            ov.x = (xv.x + cv.x) * tv.x;
            ov.y = (xv.y + cv.y) * tv.y;
            ov.z = (xv.z + cv.z) * tv.z;
            ov.w = (xv.w + cv.w) * tv.w;
            *(float4*)(ob + (size_t)co * HW + h * WW + 4 * lane) = ov;
        }

        __syncthreads();   // convbuf/t4buf reads done; T stage visible
        row = nrow;
    }
}

extern "C" void kernel_launch(void* const* d_in, const int* in_sizes, int n_in,
                              void* d_out, int out_size) {
    const float* x     = (const float*)d_in[0];
    const float* wconv = (const float*)d_in[1];
    const float* p4    = (const float*)d_in[2];
    float* out         = (float*)d_out;

    (void)in_sizes; (void)n_in; (void)out_size;

    cudaFuncSetAttribute(fused_conv_mma_kernel,
                         cudaFuncAttributeMaxDynamicSharedMemorySize, SMEM_DYN);

    int dev = 0, sms = 148;
    cudaGetDevice(&dev);
    cudaDeviceGetAttribute(&sms, cudaDevAttrMultiProcessorCount, dev);

    fused_conv_mma_kernel<<<sms, NTHREADS, SMEM_DYN>>>(x, wconv, p4, out);
}

// round 15
// speedup vs baseline: 1.6989x; 1.6989x over previous
#include <cuda_runtime.h>
#include <cstdint>

#define CCH 64
#define HH 128
#define WW 128
#define NBATCH 32
#define KW 7
#define NTHREADS 1024
#define TOTAL_ROWS (NBATCH * HH)
#define HALF_ROWS (TOTAL_ROWS / 2)     // 2048; pair partner = row + HALF_ROWS
#define HW (HH * WW)

// smem layout (bytes)
#define B_BYTES (KW * 8 * 4 * 32 * 16)        // 114688: [j][kt][ntp][lane] uint4
#define TOFF B_BYTES
#define T_STRIDE 68                            // uint32 per T row (64 ci + 4 pad)
#define T_ROWS 146
#define T_BYTES (T_ROWS * T_STRIDE * 4)        // 39712 (two buffers: rows A and B)
#define CONVOFF (TOFF + 2 * T_BYTES)           // 194112
#define BUF_STRIDE 132                         // floats per co row (128 + 4 pad)
#define BUF_BYTES (CCH * BUF_STRIDE * 4)       // 33792
#define SMEM_DYN (CONVOFF + BUF_BYTES)         // 227904

__device__ __forceinline__ uint32_t f2tf32(float f) {
    uint32_t r;
    asm("cvt.rna.tf32.f32 %0, %1;" : "=r"(r) : "f"(f));
    return r;
}

__device__ __forceinline__ void mma_tf32(float* d,
                                         uint32_t a0, uint32_t a1,
                                         uint32_t a2, uint32_t a3,
                                         uint32_t b0, uint32_t b1) {
    asm volatile(
        "mma.sync.aligned.m16n8k8.row.col.f32.tf32.tf32.f32 "
        "{%0,%1,%2,%3}, {%4,%5,%6,%7}, {%8,%9}, {%0,%1,%2,%3};"
        : "+f"(d[0]), "+f"(d[1]), "+f"(d[2]), "+f"(d[3])
        : "r"(a0), "r"(a1), "r"(a2), "r"(a3), "r"(b0), "r"(b1));
}

// Stage x[n][:, h, :] -> T[buf] as tf32, transposed [w+9][ci]. 1024 threads.
__device__ __forceinline__ void stage_T(char* smem, const float* __restrict__ x,
                                        int n, int h, int buf) {
    const int tid = threadIdx.x;
    uint32_t* Tb = (uint32_t*)(smem + TOFF + buf * T_BYTES);
    const float* xrow = x + ((size_t)(n * CCH) * HH + h) * WW;
    const int ci = tid & 63;
    const int w0 = tid >> 6;                   // 0..15
    #pragma unroll
    for (int it = 0; it < 2; ++it) {
        const int wg = w0 + 16 * it;           // 0..31
        const float4 v = __ldg((const float4*)(xrow + (size_t)ci * HW + wg * 4));
        uint32_t* dst = Tb + (4 * wg + 9) * T_STRIDE + ci;
        dst[0 * T_STRIDE] = f2tf32(v.x);
        dst[1 * T_STRIDE] = f2tf32(v.y);
        dst[2 * T_STRIDE] = f2tf32(v.z);
        dst[3 * T_STRIDE] = f2tf32(v.w);
    }
}

// Dump one row's accumulators into convbuf.
__device__ __forceinline__ void dump_row(float* convbuf, const float acc[2][4],
                                         int mw, int g2, int lane) {
    #pragma unroll
    for (int half = 0; half < 2; ++half) {
        const int w = mw * 16 + half * 8 + (lane >> 2);
        #pragma unroll
        for (int nt = 0; nt < 2; ++nt)
            #pragma unroll
            for (int q = 0; q < 2; ++q) {
                const int co = 16 * g2 + nt * 8 + 2 * (lane & 3) + q;
                convbuf[co * BUF_STRIDE + w] = acc[nt][half * 2 + q];
            }
    }
}

// Out phase for one row: out = (x + conv) * t4, t4 computed inline via shfl.
__device__ __forceinline__ void out_row(const float* convbuf,
                                        const float* __restrict__ x,
                                        float* __restrict__ out,
                                        int n, int h, int warp, int lane,
                                        float p40, float p41, float p42) {
    const float* xb = x + (size_t)n * CCH * HW;
    float* ob = out + (size_t)n * CCH * HW;
    const int hm1 = (h - 1 + HH) & (HH - 1);
    const int r0 = hm1 - 2, r2 = hm1 + 2;
    const bool has0 = (r0 >= 0), has2 = (r2 < HH);
    const int src = (lane + 1) & 31;
    #pragma unroll
    for (int i = 0; i < 2; ++i) {
        const int co = warp + 32 * i;
        const float* xc = xb + (size_t)co * HW;
        // t4 for w = 4*lane + e needs x[..][wp], wp = (4*lane + e + 2) & 127
        float4 t4v;
        {
            const float4 f = __ldg((const float4*)(xc + hm1 * WW + 4 * lane));
            const float nx = __shfl_sync(0xffffffffu, f.x, src);
            const float ny = __shfl_sync(0xffffffffu, f.y, src);
            t4v.x = p41 * f.z; t4v.y = p41 * f.w;
            t4v.z = p41 * nx;  t4v.w = p41 * ny;
        }
        if (has0) {
            const float4 f = __ldg((const float4*)(xc + r0 * WW + 4 * lane));
            const float nx = __shfl_sync(0xffffffffu, f.x, src);
            const float ny = __shfl_sync(0xffffffffu, f.y, src);
            t4v.x = fmaf(p40, f.z, t4v.x); t4v.y = fmaf(p40, f.w, t4v.y);
            t4v.z = fmaf(p40, nx, t4v.z);  t4v.w = fmaf(p40, ny, t4v.w);
        }
        if (has2) {
            const float4 f = __ldg((const float4*)(xc + r2 * WW + 4 * lane));
            const float nx = __shfl_sync(0xffffffffu, f.x, src);
            const float ny = __shfl_sync(0xffffffffu, f.y, src);
            t4v.x = fmaf(p42, f.z, t4v.x); t4v.y = fmaf(p42, f.w, t4v.y);
            t4v.z = fmaf(p42, nx, t4v.z);  t4v.w = fmaf(p42, ny, t4v.w);
        }
        const float4 cv = *(const float4*)(convbuf + co * BUF_STRIDE + 4 * lane);
        const float4 xv = __ldg((const float4*)(xc + h * WW + 4 * lane));
        float4 ov;
        ov.x = (xv.x + cv.x) * t4v.x;
        ov.y = (xv.y + cv.y) * t4v.y;
        ov.z = (xv.z + cv.z) * t4v.z;
        ov.w = (xv.w + cv.w) * t4v.w;
        *(float4*)(ob + (size_t)co * HW + h * WW + 4 * lane) = ov;
    }
}

extern "C" __global__ void __launch_bounds__(NTHREADS, 1)
fused_conv_mma_kernel(const float* __restrict__ x,
                      const float* __restrict__ wconv,
                      const float* __restrict__ p4,
                      float* __restrict__ out) {
    extern __shared__ char smem[];
    const int tid = threadIdx.x;
    const int lane = tid & 31;
    const int warp = tid >> 5;                 // 0..31
    const int g2 = warp >> 3;                  // co-quarter (16 co)
    const int mw = warp & 7;                   // m-stripe (16 w rows)

    // ---- one-time: pack B fragments [j][kt][ntp][lane] = uint4 ----
    for (int idx = tid; idx < KW * 8 * 4 * 32; idx += NTHREADS) {
        const int t   = idx & 31;
        const int ntp = (idx >> 5) & 3;
        const int kt  = (idx >> 7) & 7;
        const int j   = idx >> 10;
        const int n_in = t >> 2;
        const int k_in = t & 3;
        const int ci0 = kt * 8 + k_in, ci1 = ci0 + 4;
        const int coA = 16 * ntp + n_in, coB = coA + 8;
        uint4 v;
        v.x = f2tf32(__ldg(wconv + (coA * CCH + ci0) * KW + j));
        v.y = f2tf32(__ldg(wconv + (coA * CCH + ci1) * KW + j));
        v.z = f2tf32(__ldg(wconv + (coB * CCH + ci0) * KW + j));
        v.w = f2tf32(__ldg(wconv + (coB * CCH + ci1) * KW + j));
        ((uint4*)smem)[idx] = v;
    }
    // zero both T buffers (pad rows stay zero forever)
    for (int i = tid; i < 2 * T_ROWS * T_STRIDE; i += NTHREADS)
        ((uint32_t*)(smem + TOFF))[i] = 0;

    const float p40 = __ldg(p4 + 0), p41 = __ldg(p4 + 1), p42 = __ldg(p4 + 2);

    __syncthreads();
    int row = blockIdx.x;                      // pairs: (row, row + HALF_ROWS)
    if (row < HALF_ROWS) {
        stage_T(smem, x, row >> 7, row & (HH - 1), 0);
        stage_T(smem, x, (row + HALF_ROWS) >> 7, row & (HH - 1), 1);
    }
    __syncthreads();

    const uint4* Bfr = (const uint4*)smem;
    float* convbuf = (float*)(smem + CONVOFF);

    while (row < HALF_ROWS) {
        const int h  = row & (HH - 1);
        const int nA = row >> 7;
        const int nB = nA + (HALF_ROWS >> 7);  // +16 images

        // ---- MMA: both rows share B loads. acc[r][nt][4] ----
        float acc[2][2][4];
        #pragma unroll
        for (int r = 0; r < 2; ++r)
            #pragma unroll
            for (int nt = 0; nt < 2; ++nt)
                #pragma unroll
                for (int q = 0; q < 4; ++q) acc[r][nt][q] = 0.0f;

        {
            const uint32_t* TA = (const uint32_t*)(smem + TOFF);
            const uint32_t* TB = (const uint32_t*)(smem + TOFF + T_BYTES);
            const int rbase = mw * 16 + (lane >> 2);
            const int cbase = lane & 3;
            #pragma unroll 1
            for (int j = 0; j < KW; ++j) {
                const int roff = (rbase + 3 * j) * T_STRIDE + cbase;
                const uint32_t* TrA = TA + roff;
                const uint32_t* TrB = TB + roff;
                const uint4* Bj = Bfr + j * 1024 + 32 * g2 + lane;
                #pragma unroll
                for (int kt = 0; kt < 8; ++kt) {
                    const uint4 b01 = Bj[kt * 128];
                    {
                        const uint32_t* Tc = TrA + kt * 8;
                        const uint32_t a0 = Tc[0];
                        const uint32_t a1 = Tc[8 * T_STRIDE];
                        const uint32_t a2 = Tc[4];
                        const uint32_t a3 = Tc[8 * T_STRIDE + 4];
                        mma_tf32(acc[0][0], a0, a1, a2, a3, b01.x, b01.y);
                        mma_tf32(acc[0][1], a0, a1, a2, a3, b01.z, b01.w);
                    }
                    {
                        const uint32_t* Tc = TrB + kt * 8;
                        const uint32_t a0 = Tc[0];
                        const uint32_t a1 = Tc[8 * T_STRIDE];
                        const uint32_t a2 = Tc[4];
                        const uint32_t a3 = Tc[8 * T_STRIDE + 4];
                        mma_tf32(acc[1][0], a0, a1, a2, a3, b01.x, b01.y);
                        mma_tf32(acc[1][1], a0, a1, a2, a3, b01.z, b01.w);
                    }
                }
            }
        }

        const int nrow = row + gridDim.x;

        // ---- row A: dump, sync, out + stage next-A ----
        dump_row(convbuf, acc[0], mw, g2, lane);
        __syncthreads();

        out_row(convbuf, x, out, nA, h, warp, lane, p40, p41, p42);
        if (nrow < HALF_ROWS)
            stage_T(smem, x, nrow >> 7, nrow & (HH - 1), 0);
        __syncthreads();

        // ---- row B: dump, sync, out + stage next-B ----
        dump_row(convbuf, acc[1], mw, g2, lane);
        __syncthreads();

        out_row(convbuf, x, out, nB, h, warp, lane, p40, p41, p42);
        if (nrow < HALF_ROWS)
            stage_T(smem, x, (nrow + HALF_ROWS) >> 7, nrow & (HH - 1), 1);
        __syncthreads();

        row = nrow;
    }
}

extern "C" void kernel_launch(void* const* d_in, const int* in_sizes, int n_in,
                              void* d_out, int out_size) {
    const float* x     = (const float*)d_in[0];
    const float* wconv = (const float*)d_in[1];
    const float* p4    = (const float*)d_in[2];
    float* out         = (float*)d_out;

    (void)in_sizes; (void)n_in; (void)out_size;

    cudaFuncSetAttribute(fused_conv_mma_kernel,
                         cudaFuncAttributeMaxDynamicSharedMemorySize, SMEM_DYN);

    int dev = 0, sms = 148;
    cudaGetDevice(&dev);
    cudaDeviceGetAttribute(&sms, cudaDevAttrMultiProcessorCount, dev);

    fused_conv_mma_kernel<<<sms, NTHREADS, SMEM_DYN>>>(x, wconv, p4, out);
}

// round 16
// speedup vs baseline: 1.8744x; 1.1033x over previous
#include <cuda_runtime.h>
#include <cstdint>

#define CCH 64
#define HH 128
#define WW 128
#define NBATCH 32
#define KW 7
#define NTHREADS 1024
#define TOTAL_ROWS (NBATCH * HH)
#define HALF_ROWS (TOTAL_ROWS / 2)     // 2048; pair partner = row + HALF_ROWS
#define HW (HH * WW)

// smem layout (bytes)
#define B_BYTES (KW * 8 * 4 * 32 * 16)        // 114688: [j][kt][ntp][lane] uint4
#define TOFF B_BYTES
#define T_STRIDE 68                            // uint32 per T row (64 ci + 4 pad)
#define T_ROWS 146
#define T_BYTES (T_ROWS * T_STRIDE * 4)        // 39712 (T0, T1)
#define CONVOFF (TOFF + 2 * T_BYTES)           // 194112: convA (row A)
#define BUF_STRIDE 132                         // floats per co row (128 + 4 pad)
#define BUF_BYTES (CCH * BUF_STRIDE * 4)       // 33792
#define SMEM_DYN (CONVOFF + BUF_BYTES)         // 227904
// convB lives inside T1's data rows (rows 9..133), preserving zero-pad rows:
//   T1 base = TOFF + T_BYTES; pad rows 0..8 end at byte 9*272 = 2448;
//   convB = T1 + 2448, size 33792, ends at 36240 <= 37264 (= row 137 start).
#define CONVB_OFF (TOFF + T_BYTES + 2448)

__device__ __forceinline__ uint32_t f2tf32(float f) {
    uint32_t r;
    asm("cvt.rna.tf32.f32 %0, %1;" : "=r"(r) : "f"(f));
    return r;
}

__device__ __forceinline__ void mma_tf32(float* d,
                                         uint32_t a0, uint32_t a1,
                                         uint32_t a2, uint32_t a3,
                                         uint32_t b0, uint32_t b1) {
    asm volatile(
        "mma.sync.aligned.m16n8k8.row.col.f32.tf32.tf32.f32 "
        "{%0,%1,%2,%3}, {%4,%5,%6,%7}, {%8,%9}, {%0,%1,%2,%3};"
        : "+f"(d[0]), "+f"(d[1]), "+f"(d[2]), "+f"(d[3])
        : "r"(a0), "r"(a1), "r"(a2), "r"(a3), "r"(b0), "r"(b1));
}

// Fully-static 28-step K-half. TA/TB pre-offset to (rbase*T_STRIDE + cbase).
// Bw pre-offset to (64*g + lane). All per-step offsets are compile-time.
template <int S0>
__device__ __forceinline__ void mma_kspan(float acc[2][4][4],
                                          const uint32_t* __restrict__ TA,
                                          const uint32_t* __restrict__ TB,
                                          const uint4* __restrict__ Bw) {
    #pragma unroll
    for (int s = S0; s < S0 + 28; ++s) {
        const int j  = s >> 3;
        const int kt = s & 7;
        const int to = 3 * j * T_STRIDE + kt * 8;
        const int bo = j * 1024 + kt * 128;
        const uint4 b01 = Bw[bo];
        const uint4 b23 = Bw[bo + 32];
        {
            const uint32_t a0 = TA[to];
            const uint32_t a1 = TA[to + 8 * T_STRIDE];
            const uint32_t a2 = TA[to + 4];
            const uint32_t a3 = TA[to + 8 * T_STRIDE + 4];
            mma_tf32(acc[0][0], a0, a1, a2, a3, b01.x, b01.y);
            mma_tf32(acc[0][1], a0, a1, a2, a3, b01.z, b01.w);
            mma_tf32(acc[0][2], a0, a1, a2, a3, b23.x, b23.y);
            mma_tf32(acc[0][3], a0, a1, a2, a3, b23.z, b23.w);
        }
        {
            const uint32_t a0 = TB[to];
            const uint32_t a1 = TB[to + 8 * T_STRIDE];
            const uint32_t a2 = TB[to + 4];
            const uint32_t a3 = TB[to + 8 * T_STRIDE + 4];
            mma_tf32(acc[1][0], a0, a1, a2, a3, b01.x, b01.y);
            mma_tf32(acc[1][1], a0, a1, a2, a3, b01.z, b01.w);
            mma_tf32(acc[1][2], a0, a1, a2, a3, b23.x, b23.y);
            mma_tf32(acc[1][3], a0, a1, a2, a3, b23.z, b23.w);
        }
    }
}

// Stage x[n][:, h, :] -> T[buf], 512 threads (id 0..511).
__device__ __forceinline__ void stage_T(char* smem, const float* __restrict__ x,
                                        int n, int h, int buf, int id) {
    uint32_t* Tb = (uint32_t*)(smem + TOFF + buf * T_BYTES);
    const float* xrow = x + ((size_t)(n * CCH) * HH + h) * WW;
    const int ci = id & 63;
    const int w0 = id >> 6;                    // 0..7
    #pragma unroll
    for (int it = 0; it < 4; ++it) {
        const int wg = w0 + 8 * it;            // 0..31
        const float4 v = __ldg((const float4*)(xrow + (size_t)ci * HW + wg * 4));
        uint32_t* dst = Tb + (4 * wg + 9) * T_STRIDE + ci;
        dst[0 * T_STRIDE] = f2tf32(v.x);
        dst[1 * T_STRIDE] = f2tf32(v.y);
        dst[2 * T_STRIDE] = f2tf32(v.z);
        dst[3 * T_STRIDE] = f2tf32(v.w);
    }
}

// Dump (st=1) or merge (st=0) one row's partials into a conv buffer.
template <int STORE>
__device__ __forceinline__ void dump_row(float* convbuf, const float acc[4][4],
                                         int mw, int g, int lane) {
    #pragma unroll
    for (int half = 0; half < 2; ++half) {
        const int w = mw * 16 + half * 8 + (lane >> 2);
        #pragma unroll
        for (int nt = 0; nt < 4; ++nt)
            #pragma unroll
            for (int q = 0; q < 2; ++q) {
                const int co = 32 * g + nt * 8 + 2 * (lane & 3) + q;
                float* p = convbuf + co * BUF_STRIDE + w;
                if (STORE) *p = acc[nt][half * 2 + q];
                else       *p += acc[nt][half * 2 + q];
            }
    }
}

// out = (x + conv) * t4, t4 inline via float4 LDG + shfl.
__device__ __forceinline__ void out_row(const float* convbuf,
                                        const float* __restrict__ x,
                                        float* __restrict__ out,
                                        int n, int h, int warp, int lane,
                                        float p40, float p41, float p42) {
    const float* xb = x + (size_t)n * CCH * HW;
    float* ob = out + (size_t)n * CCH * HW;
    const int hm1 = (h - 1 + HH) & (HH - 1);
    const int r0 = hm1 - 2, r2 = hm1 + 2;
    const bool has0 = (r0 >= 0), has2 = (r2 < HH);
    const int src = (lane + 1) & 31;
    #pragma unroll
    for (int i = 0; i < 2; ++i) {
        const int co = warp + 32 * i;
        const float* xc = xb + (size_t)co * HW;
        float4 t4v;
        {
            const float4 f = __ldg((const float4*)(xc + hm1 * WW + 4 * lane));
            const float nx = __shfl_sync(0xffffffffu, f.x, src);
            const float ny = __shfl_sync(0xffffffffu, f.y, src);
            t4v.x = p41 * f.z; t4v.y = p41 * f.w;
            t4v.z = p41 * nx;  t4v.w = p41 * ny;
        }
        if (has0) {
            const float4 f = __ldg((const float4*)(xc + r0 * WW + 4 * lane));
            const float nx = __shfl_sync(0xffffffffu, f.x, src);
            const float ny = __shfl_sync(0xffffffffu, f.y, src);
            t4v.x = fmaf(p40, f.z, t4v.x); t4v.y = fmaf(p40, f.w, t4v.y);
            t4v.z = fmaf(p40, nx, t4v.z);  t4v.w = fmaf(p40, ny, t4v.w);
        }
        if (has2) {
            const float4 f = __ldg((const float4*)(xc + r2 * WW + 4 * lane));
            const float nx = __shfl_sync(0xffffffffu, f.x, src);
            const float ny = __shfl_sync(0xffffffffu, f.y, src);
            t4v.x = fmaf(p42, f.z, t4v.x); t4v.y = fmaf(p42, f.w, t4v.y);
            t4v.z = fmaf(p42, nx, t4v.z);  t4v.w = fmaf(p42, ny, t4v.w);
        }
        const float4 cv = *(const float4*)(convbuf + co * BUF_STRIDE + 4 * lane);
        const float4 xv = __ldg((const float4*)(xc + h * WW + 4 * lane));
        float4 ov;
        ov.x = (xv.x + cv.x) * t4v.x;
        ov.y = (xv.y + cv.y) * t4v.y;
        ov.z = (xv.z + cv.z) * t4v.z;
        ov.w = (xv.w + cv.w) * t4v.w;
        *(float4*)(ob + (size_t)co * HW + h * WW + 4 * lane) = ov;
    }
}

extern "C" __global__ void __launch_bounds__(NTHREADS, 1)
fused_conv_mma_kernel(const float* __restrict__ x,
                      const float* __restrict__ wconv,
                      const float* __restrict__ p4,
                      float* __restrict__ out) {
    extern __shared__ char smem[];
    const int tid = threadIdx.x;
    const int lane = tid & 31;
    const int warp = tid >> 5;                 // 0..31
    const int kh = warp >> 4;                  // K-half
    const int g  = (warp >> 3) & 1;            // co-half
    const int mw = warp & 7;                   // m-stripe (16 w rows)

    // ---- one-time: pack B fragments [j][kt][ntp][lane] = uint4 ----
    for (int idx = tid; idx < KW * 8 * 4 * 32; idx += NTHREADS) {
        const int t   = idx & 31;
        const int ntp = (idx >> 5) & 3;
        const int kt  = (idx >> 7) & 7;
        const int j   = idx >> 10;
        const int n_in = t >> 2;
        const int k_in = t & 3;
        const int ci0 = kt * 8 + k_in, ci1 = ci0 + 4;
        const int coA = 16 * ntp + n_in, coB = coA + 8;
        uint4 v;
        v.x = f2tf32(__ldg(wconv + (coA * CCH + ci0) * KW + j));
        v.y = f2tf32(__ldg(wconv + (coA * CCH + ci1) * KW + j));
        v.z = f2tf32(__ldg(wconv + (coB * CCH + ci0) * KW + j));
        v.w = f2tf32(__ldg(wconv + (coB * CCH + ci1) * KW + j));
        ((uint4*)smem)[idx] = v;
    }
    // zero both T buffers (pads stay zero; convB trampling avoids pad rows)
    for (int i = tid; i < 2 * T_ROWS * T_STRIDE; i += NTHREADS)
        ((uint32_t*)(smem + TOFF))[i] = 0;

    const float p40 = __ldg(p4 + 0), p41 = __ldg(p4 + 1), p42 = __ldg(p4 + 2);

    __syncthreads();
    int row = blockIdx.x;                      // pairs: (row, row + HALF_ROWS)
    if (row < HALF_ROWS) {
        if (tid < 512)
            stage_T(smem, x, row >> 7, row & (HH - 1), 0, tid);
        else
            stage_T(smem, x, (row + HALF_ROWS) >> 7, row & (HH - 1), 1, tid - 512);
    }
    __syncthreads();

    const uint4* Bfr = (const uint4*)smem;
    float* convA = (float*)(smem + CONVOFF);
    float* convB = (float*)(smem + CONVB_OFF);

    while (row < HALF_ROWS) {
        const int h  = row & (HH - 1);
        const int nA = row >> 7;
        const int nB = nA + (HALF_ROWS >> 7);  // +16 images

        // ---- P1: MMA, all 32 warps, static K-half each ----
        float acc[2][2][4][4];                 // [dummy compat] -> use [2][4][4]
        float (*accp)[4][4] = (float(*)[4][4])acc;   // acc[0]=rowA, acc[1]=rowB
        #pragma unroll
        for (int r = 0; r < 2; ++r)
            #pragma unroll
            for (int nt = 0; nt < 4; ++nt)
                #pragma unroll
                for (int q = 0; q < 4; ++q) accp[r][nt][q] = 0.0f;

        {
            const int rbc = (mw * 16 + (lane >> 2)) * T_STRIDE + (lane & 3);
            const uint32_t* TA = (const uint32_t*)(smem + TOFF) + rbc;
            const uint32_t* TB = (const uint32_t*)(smem + TOFF + T_BYTES) + rbc;
            const uint4* Bw = Bfr + 64 * g + lane;
            if (kh == 0) mma_kspan<0>(accp, TA, TB, Bw);
            else         mma_kspan<28>(accp, TA, TB, Bw);
        }

        __syncthreads();   // T1 free: convB may now overwrite its data rows

        // ---- P2: dumpA (kh0) || dumpB (kh1) ----
        if (kh == 0) dump_row<1>(convA, accp[0], mw, g, lane);
        else         dump_row<1>(convB, accp[1], mw, g, lane);
        __syncthreads();

        // ---- P3: mergeA (kh1) || mergeB (kh0) ----
        if (kh == 0) dump_row<0>(convB, accp[1], mw, g, lane);
        else         dump_row<0>(convA, accp[0], mw, g, lane);
        __syncthreads();

        // ---- P4: out both rows (long LDG phase, good MLP) ----
        out_row(convA, x, out, nA, h, warp, lane, p40, p41, p42);
        out_row(convB, x, out, nB, h, warp, lane, p40, p41, p42);
        __syncthreads();   // conv reads done before restage tramples T1

        // ---- P5: restage both T buffers for next pair ----
        const int nrow = row + gridDim.x;
        if (nrow < HALF_ROWS) {
            if (tid < 512)
                stage_T(smem, x, nrow >> 7, nrow & (HH - 1), 0, tid);
            else
                stage_T(smem, x, (nrow + HALF_ROWS) >> 7, nrow & (HH - 1), 1,
                        tid - 512);
        }
        __syncthreads();

        row = nrow;
    }
}

extern "C" void kernel_launch(void* const* d_in, const int* in_sizes, int n_in,
                              void* d_out, int out_size) {
    const float* x     = (const float*)d_in[0];
    const float* wconv = (const float*)d_in[1];
    const float* p4    = (const float*)d_in[2];
    float* out         = (float*)d_out;

    (void)in_sizes; (void)n_in; (void)out_size;

    cudaFuncSetAttribute(fused_conv_mma_kernel,
                         cudaFuncAttributeMaxDynamicSharedMemorySize, SMEM_DYN);

    int dev = 0, sms = 148;
    cudaGetDevice(&dev);
    cudaDeviceGetAttribute(&sms, cudaDevAttrMultiProcessorCount, dev);

    fused_conv_mma_kernel<<<sms, NTHREADS, SMEM_DYN>>>(x, wconv, p4, out);
}